// round 4
// baseline (speedup 1.0000x reference)
#include <cuda_runtime.h>
#include <cuda_bf16.h>
#include <cstdint>

#define T_ 4
#define B_ 64
#define D_ 512
#define V_ 256
#define Z_ (T_*B_)            // 256
#define PLANE (B_*D_*V_)
#define TOTAL (Z_*D_*V_)      // 33554432

// ---------------- scratch ----------------
__device__ __nv_bfloat16 g_xb[TOTAL];     // x bf16, native [z][d][v]
__device__ __nv_bfloat16 g_qpre[TOTAL];   // [z][o][v]
__device__ __nv_bfloat16 g_kpre[TOTAL];   // [z][o][v]
__device__ __nv_bfloat16 g_obuf[TOTAL];   // gate*k spikes, [z][d][v]
__device__ __nv_bfloat16 g_wq[D_*D_];
__device__ __nv_bfloat16 g_wk[D_*D_];
__device__ __nv_bfloat16 g_wp[D_*D_];

// ---------------- helpers ----------------
__device__ __forceinline__ uint32_t smem_u32(const void* p) {
    uint32_t a;
    asm("{ .reg .u64 t; cvta.to.shared.u64 t, %1; cvt.u32.u64 %0, t; }" : "=r"(a) : "l"(p));
    return a;
}
__device__ __forceinline__ void cp16(uint32_t sdst, const void* gsrc) {
    asm volatile("cp.async.cg.shared.global [%0], [%1], 16;" :: "r"(sdst), "l"(gsrc) : "memory");
}
#define CP_COMMIT() asm volatile("cp.async.commit_group;" ::: "memory")
#define CP_WAIT1()  asm volatile("cp.async.wait_group 1;" ::: "memory")
#define CP_WAIT0()  asm volatile("cp.async.wait_group 0;" ::: "memory")

__device__ __forceinline__ void ldsm_x4(uint32_t* r, uint32_t addr) {
    asm volatile("ldmatrix.sync.aligned.m8n8.x4.shared.b16 {%0,%1,%2,%3}, [%4];"
        : "=r"(r[0]), "=r"(r[1]), "=r"(r[2]), "=r"(r[3]) : "r"(addr));
}
__device__ __forceinline__ void ldsm_x4_t(uint32_t* r, uint32_t addr) {
    asm volatile("ldmatrix.sync.aligned.m8n8.x4.trans.shared.b16 {%0,%1,%2,%3}, [%4];"
        : "=r"(r[0]), "=r"(r[1]), "=r"(r[2]), "=r"(r[3]) : "r"(addr));
}
__device__ __forceinline__ void mma_bf16(float* d, const uint32_t* a, uint32_t b0, uint32_t b1) {
    asm volatile("mma.sync.aligned.m16n8k16.row.col.f32.bf16.bf16.f32 "
        "{%0,%1,%2,%3}, {%4,%5,%6,%7}, {%8,%9}, {%0,%1,%2,%3};"
        : "+f"(d[0]), "+f"(d[1]), "+f"(d[2]), "+f"(d[3])
        : "r"(a[0]), "r"(a[1]), "r"(a[2]), "r"(a[3]), "r"(b0), "r"(b1));
}

// ---------------------------------------------------------------------------
// bf16 mma.sync GEMM + folded BN, output-native orientation:
//   O[z][o][v] = BN_o( sum_d W[o][d] * X[z][d][v] )
// CTA: 128 (o) x 256 (v, full width). 8 warps = 2(o) x 4(v), warp tile 64x64.
// K=512 in 16 chunks of 32, 3-stage cp.async pipeline, 1 barrier per chunk.
// A (W) K-major, ldmatrix; B (X) native [d][v], ldmatrix.trans.
// SMEM pitches: A 80B/row, B 528B/row  (bank-conflict-free phases).
// ---------------------------------------------------------------------------
#define A_STAGE 10240            // 128 rows * 80 B
#define B_STAGE 16896            // 32 rows * 528 B
#define GEMM_SMEM (3*A_STAGE + 3*B_STAGE)   // 82944

__global__ void __launch_bounds__(256, 1) gemm_bn_mma(
    const __nv_bfloat16* __restrict__ W,   // [512][512]
    const __nv_bfloat16* __restrict__ X,   // [Z][512][256]
    const float* __restrict__ gamma, const float* __restrict__ beta,
    const float* __restrict__ mean, const float* __restrict__ var,
    __nv_bfloat16* __restrict__ O)         // [Z][512][256]
{
    extern __shared__ __align__(16) char smem[];
    __shared__ float sScale[128], sBias[128];

    const int tid = threadIdx.x, wid = tid >> 5, lane = tid & 31;
    const int z = blockIdx.x, o0 = blockIdx.y * 128;

    const __nv_bfloat16* Wb = W + (size_t)o0 * D_;
    const __nv_bfloat16* Xb = X + (size_t)z * D_ * V_;

    if (tid < 128) {
        const float inv = gamma[o0 + tid] * rsqrtf(var[o0 + tid] + 1e-5f);
        sScale[tid] = inv;
        sBias[tid]  = beta[o0 + tid] - mean[o0 + tid] * inv;
    }

    const uint32_t sA = smem_u32(smem);
    const uint32_t sB = sA + 3 * A_STAGE;

    const int wm = wid & 1;      // o 64-slice
    const int wv = wid >> 1;     // v 64-slice

    float acc[4][8][4];
    #pragma unroll
    for (int i = 0; i < 4; ++i)
        #pragma unroll
        for (int j = 0; j < 8; ++j)
            #pragma unroll
            for (int q = 0; q < 4; ++q) acc[i][j][q] = 0.f;

    auto issue = [&](int s, int kc) {
        const uint32_t ab = sA + s * A_STAGE;
        const uint32_t bb = sB + s * B_STAGE;
        #pragma unroll
        for (int i = 0; i < 2; ++i) {       // A: 128 rows x 4 x 16B
            const int idx = tid + i * 256;
            const int row = idx >> 2, c = idx & 3;
            cp16(ab + row * 80 + c * 16, Wb + (size_t)row * D_ + kc + c * 8);
        }
        #pragma unroll
        for (int i = 0; i < 4; ++i) {       // B: 32 rows x 32 x 16B
            const int idx = tid + i * 256;
            const int row = idx >> 5, c = idx & 31;
            cp16(bb + row * 528 + c * 16, Xb + (size_t)(kc + row) * V_ + c * 8);
        }
        CP_COMMIT();
    };

    issue(0, 0);
    issue(1, 32);

    #pragma unroll 1
    for (int c = 0; c < 16; ++c) {
        if (c < 15) CP_WAIT1(); else CP_WAIT0();
        __syncthreads();
        if (c < 14) issue((c + 2) % 3, (c + 2) * 32);

        const int s = c % 3;
        const uint32_t aB = sA + s * A_STAGE;
        const uint32_t bB = sB + s * B_STAGE;

        #pragma unroll
        for (int kk = 0; kk < 2; ++kk) {
            uint32_t af[4][4];
            #pragma unroll
            for (int mt = 0; mt < 4; ++mt) {
                const int row = wm * 64 + mt * 16 + (lane & 15);
                ldsm_x4(af[mt], aB + row * 80 + kk * 32 + (lane >> 4) * 16);
            }
            uint32_t bf[4][4];
            const int sub = lane >> 3;
            const int krow = kk * 16 + (sub & 1) * 8 + (lane & 7);
            #pragma unroll
            for (int g = 0; g < 4; ++g) {
                const int ncol = wv * 64 + g * 16 + (sub >> 1) * 8;
                ldsm_x4_t(bf[g], bB + krow * 528 + ncol * 2);
            }
            #pragma unroll
            for (int mt = 0; mt < 4; ++mt)
                #pragma unroll
                for (int g = 0; g < 4; ++g) {
                    mma_bf16(acc[mt][g * 2 + 0], af[mt], bf[g][0], bf[g][1]);
                    mma_bf16(acc[mt][g * 2 + 1], af[mt], bf[g][2], bf[g][3]);
                }
        }
    }

    // epilogue: BN -> bf16x2 stores, output row = o (v contiguous)
    #pragma unroll
    for (int mt = 0; mt < 4; ++mt) {
        const int oL = wm * 64 + mt * 16 + (lane >> 2);
        #pragma unroll
        for (int h = 0; h < 2; ++h) {
            const int o = oL + h * 8;
            const float sc = sScale[o], bi = sBias[o];
            __nv_bfloat16* orow = O + ((size_t)z * D_ + o0 + o) * V_;
            #pragma unroll
            for (int nt = 0; nt < 8; ++nt) {
                const int v = wv * 64 + nt * 8 + (lane & 3) * 2;
                const float fa = acc[mt][nt][2 * h]     * sc + bi;
                const float fb = acc[mt][nt][2 * h + 1] * sc + bi;
                const __nv_bfloat162 h2 = __floats2bfloat162_rn(fa, fb);
                *(uint32_t*)(orow + v) = *(const uint32_t*)&h2;
            }
        }
    }
}

// ---------------------------------------------------------------------------
// x fp32 -> bf16, same layout
// ---------------------------------------------------------------------------
__global__ void convert_x_kernel(const float* __restrict__ x, __nv_bfloat16* __restrict__ xb) {
    const size_t i = (size_t)blockIdx.x * blockDim.x + threadIdx.x;   // over TOTAL/2
    const float2 f = ((const float2*)x)[i];
    const __nv_bfloat162 h2 = __floats2bfloat162_rn(f.x, f.y);
    ((uint32_t*)xb)[i] = *(const uint32_t*)&h2;
}

__global__ void convert_w_kernel(const float* __restrict__ s, __nv_bfloat16* __restrict__ d) {
    const int i = blockIdx.x * 256 + threadIdx.x;
    d[i] = __float2bfloat16(s[i]);
}

// ---------------------------------------------------------------------------
// LIF(q) -> per-head q_sum -> gate LIF(0.5) -> LIF(k) -> out = gate*k
// Layout [z][d][v] (v contiguous), z = t*B+b. Grid (b, h), 256 threads (v).
// Per-thread d-reduction: no shuffles, no atomics.
// ---------------------------------------------------------------------------
__global__ void lif_gate_kernel(const __nv_bfloat16* __restrict__ q,
                                const __nv_bfloat16* __restrict__ k,
                                __nv_bfloat16* __restrict__ out) {
    const int b = blockIdx.x, h = blockIdx.y;
    const int v = threadIdx.x;

    float qs0 = 0.f, qs1 = 0.f, qs2 = 0.f, qs3 = 0.f;

#define IDX(t, d) ((((size_t)((t) * B_ + b)) * D_ + h * 128 + (d)) * V_ + v)
    #pragma unroll 4
    for (int d = 0; d < 128; ++d) {
        float vm = 0.f, s;
        vm = (vm + __bfloat162float(q[IDX(0, d)])) * 0.5f;
        s = (vm >= 1.f) ? 1.f : 0.f; qs0 += s; vm *= (1.f - s);
        vm = (vm + __bfloat162float(q[IDX(1, d)])) * 0.5f;
        s = (vm >= 1.f) ? 1.f : 0.f; qs1 += s; vm *= (1.f - s);
        vm = (vm + __bfloat162float(q[IDX(2, d)])) * 0.5f;
        s = (vm >= 1.f) ? 1.f : 0.f; qs2 += s; vm *= (1.f - s);
        vm = (vm + __bfloat162float(q[IDX(3, d)])) * 0.5f;
        s = (vm >= 1.f) ? 1.f : 0.f; qs3 += s;
    }

    float gate[4];
    {
        float vg = 0.f;
        const float qs[4] = {qs0, qs1, qs2, qs3};
        #pragma unroll
        for (int t = 0; t < 4; ++t) {
            vg = (vg + qs[t]) * 0.5f;
            gate[t] = (vg >= 0.5f) ? 1.f : 0.f;
            vg *= (1.f - gate[t]);
        }
    }

    #pragma unroll 4
    for (int d = 0; d < 128; ++d) {
        float vm = 0.f;
        #pragma unroll
        for (int t = 0; t < 4; ++t) {
            vm = (vm + __bfloat162float(k[IDX(t, d)])) * 0.5f;
            const float s = (vm >= 1.f) ? 1.f : 0.f;
            out[IDX(t, d)] = __float2bfloat16(gate[t] * s);
            vm *= (1.f - s);
        }
    }
#undef IDX
}

// ---------------------------------------------------------------------------
// Final LIF(1.0) over t, [z][o][v] bf16 -> d_out [t][b][o][v] fp32 (identical
// linear layout: direct elementwise, 2-wide vectorized).
// ---------------------------------------------------------------------------
__global__ void lif_final_kernel(const __nv_bfloat16* __restrict__ pre, float* __restrict__ out) {
    const size_t i2 = (size_t)blockIdx.x * blockDim.x + threadIdx.x;   // over PLANE/2
    float v0 = 0.f, v1 = 0.f;
    #pragma unroll
    for (int t = 0; t < 4; ++t) {
        const uint32_t u = ((const uint32_t*)(pre + (size_t)t * PLANE))[i2];
        const __nv_bfloat162 h2 = *(const __nv_bfloat162*)&u;
        v0 = (v0 + __bfloat162float(h2.x)) * 0.5f;
        v1 = (v1 + __bfloat162float(h2.y)) * 0.5f;
        const float s0 = (v0 >= 1.f) ? 1.f : 0.f;
        const float s1 = (v1 >= 1.f) ? 1.f : 0.f;
        ((float2*)(out + (size_t)t * PLANE))[i2] = make_float2(s0, s1);
        v0 *= (1.f - s0); v1 *= (1.f - s1);
    }
}

// ---------------------------------------------------------------------------
extern "C" void kernel_launch(void* const* d_in, const int* in_sizes, int n_in,
                              void* d_out, int out_size) {
    const float* x  = (const float*)d_in[0];
    const float* Wq = (const float*)d_in[1];
    const float* qg = (const float*)d_in[2];
    const float* qb = (const float*)d_in[3];
    const float* qm = (const float*)d_in[4];
    const float* qv = (const float*)d_in[5];
    const float* Wk = (const float*)d_in[6];
    const float* kg = (const float*)d_in[7];
    const float* kb = (const float*)d_in[8];
    const float* km = (const float*)d_in[9];
    const float* kv = (const float*)d_in[10];
    const float* Wp = (const float*)d_in[11];
    const float* pg = (const float*)d_in[12];
    const float* pb = (const float*)d_in[13];
    const float* pm = (const float*)d_in[14];
    const float* pv = (const float*)d_in[15];
    float* out = (float*)d_out;

    __nv_bfloat16 *xb, *qp, *kp, *ob, *wq, *wk, *wp;
    cudaGetSymbolAddress((void**)&xb, g_xb);
    cudaGetSymbolAddress((void**)&qp, g_qpre);
    cudaGetSymbolAddress((void**)&kp, g_kpre);
    cudaGetSymbolAddress((void**)&ob, g_obuf);
    cudaGetSymbolAddress((void**)&wq, g_wq);
    cudaGetSymbolAddress((void**)&wk, g_wk);
    cudaGetSymbolAddress((void**)&wp, g_wp);

    cudaFuncSetAttribute(gemm_bn_mma, cudaFuncAttributeMaxDynamicSharedMemorySize, GEMM_SMEM);

    convert_w_kernel<<<D_ * D_ / 256, 256>>>(Wq, wq);
    convert_w_kernel<<<D_ * D_ / 256, 256>>>(Wk, wk);
    convert_w_kernel<<<D_ * D_ / 256, 256>>>(Wp, wp);
    convert_x_kernel<<<TOTAL / 512, 256>>>(x, xb);

    dim3 gg(Z_, D_ / 128);   // (256, 4)
    gemm_bn_mma<<<gg, 256, GEMM_SMEM>>>(wq, xb, qg, qb, qm, qv, qp);
    gemm_bn_mma<<<gg, 256, GEMM_SMEM>>>(wk, xb, kg, kb, km, kv, kp);
    lif_gate_kernel<<<dim3(B_, 4), 256>>>(qp, kp, ob);
    gemm_bn_mma<<<gg, 256, GEMM_SMEM>>>(wp, ob, pg, pb, pm, pv, qp);
    lif_final_kernel<<<PLANE / 512, 256>>>(qp, out);
}

// round 5
// speedup vs baseline: 1.2202x; 1.2202x over previous
#include <cuda_runtime.h>
#include <cuda_bf16.h>
#include <cuda_fp8.h>
#include <cstdint>

#define T_ 4
#define B_ 64
#define D_ 512
#define V_ 256
#define Z_ (T_*B_)            // 256
#define PLANE (B_*D_*V_)
#define TOTAL (Z_*D_*V_)      // 33554432

// ---------------- scratch ----------------
__device__ __nv_bfloat16 g_xb[TOTAL];     // x bf16, native [z][d][v]
__device__ __nv_bfloat16 g_qpre[TOTAL];   // [z][o][v]
__device__ __nv_bfloat16 g_kpre[TOTAL];   // [z][o][v] (reused for stage-3 pre)
__device__ uint8_t       g_sp8[TOTAL];    // gate*k spikes e4m3, [z][v][d]
__device__ __nv_bfloat16 g_wq[D_*D_];
__device__ __nv_bfloat16 g_wk[D_*D_];
__device__ uint8_t       g_wp8[D_*D_];    // Wp e4m3 [o][d]

// ---------------- helpers ----------------
__device__ __forceinline__ uint32_t smem_u32(const void* p) {
    uint32_t a;
    asm("{ .reg .u64 t; cvta.to.shared.u64 t, %1; cvt.u32.u64 %0, t; }" : "=r"(a) : "l"(p));
    return a;
}
__device__ __forceinline__ void cp16(uint32_t sdst, const void* gsrc) {
    asm volatile("cp.async.cg.shared.global [%0], [%1], 16;" :: "r"(sdst), "l"(gsrc) : "memory");
}
#define CP_COMMIT() asm volatile("cp.async.commit_group;" ::: "memory")
#define CP_WAIT1()  asm volatile("cp.async.wait_group 1;" ::: "memory")
#define CP_WAIT0()  asm volatile("cp.async.wait_group 0;" ::: "memory")

__device__ __forceinline__ void ldsm_x4(uint32_t* r, uint32_t addr) {
    asm volatile("ldmatrix.sync.aligned.m8n8.x4.shared.b16 {%0,%1,%2,%3}, [%4];"
        : "=r"(r[0]), "=r"(r[1]), "=r"(r[2]), "=r"(r[3]) : "r"(addr));
}
__device__ __forceinline__ void ldsm_x4_t(uint32_t* r, uint32_t addr) {
    asm volatile("ldmatrix.sync.aligned.m8n8.x4.trans.shared.b16 {%0,%1,%2,%3}, [%4];"
        : "=r"(r[0]), "=r"(r[1]), "=r"(r[2]), "=r"(r[3]) : "r"(addr));
}
__device__ __forceinline__ void mma_bf16(float* d, const uint32_t* a, uint32_t b0, uint32_t b1) {
    asm volatile("mma.sync.aligned.m16n8k16.row.col.f32.bf16.bf16.f32 "
        "{%0,%1,%2,%3}, {%4,%5,%6,%7}, {%8,%9}, {%0,%1,%2,%3};"
        : "+f"(d[0]), "+f"(d[1]), "+f"(d[2]), "+f"(d[3])
        : "r"(a[0]), "r"(a[1]), "r"(a[2]), "r"(a[3]), "r"(b0), "r"(b1));
}
__device__ __forceinline__ void mma_fp8(float* d, const uint32_t* a, uint32_t b0, uint32_t b1) {
    asm volatile("mma.sync.aligned.m16n8k32.row.col.f32.e4m3.e4m3.f32 "
        "{%0,%1,%2,%3}, {%4,%5,%6,%7}, {%8,%9}, {%0,%1,%2,%3};"
        : "+f"(d[0]), "+f"(d[1]), "+f"(d[2]), "+f"(d[3])
        : "r"(a[0]), "r"(a[1]), "r"(a[2]), "r"(a[3]), "r"(b0), "r"(b1));
}

// ---------------------------------------------------------------------------
// Stage-1/2 GEMM (bf16) + folded BN:
//   O[z][o][v] = BN_o( sum_d W[o][d] * X[z][d][v] )
// CTA 128(o) x 128(v); 8 warps = 4(o:32) x 2(v:64); 3-stage cp.async;
// 2 CTAs/SM. A pitch 80B, B pitch 272B (conflict-free).
// ---------------------------------------------------------------------------
#define A_STG 10240            // 128 rows * 80 B
#define B_STG 8704             // 32 rows * 272 B
#define SMEM_BF16 (3*(A_STG + B_STG))   // 56832

__global__ void __launch_bounds__(256, 2) gemm_bn_bf16(
    const __nv_bfloat16* __restrict__ W,
    const __nv_bfloat16* __restrict__ X,
    const float* __restrict__ gamma, const float* __restrict__ beta,
    const float* __restrict__ mean, const float* __restrict__ var,
    __nv_bfloat16* __restrict__ O)
{
    extern __shared__ __align__(16) char smem[];
    __shared__ float sScale[128], sBias[128];

    const int tid = threadIdx.x, wid = tid >> 5, lane = tid & 31;
    const int z = blockIdx.x, o0 = blockIdx.y * 128, v0 = blockIdx.z * 128;

    const __nv_bfloat16* Wb = W + (size_t)o0 * D_;
    const __nv_bfloat16* Xb = X + (size_t)z * D_ * V_ + v0;

    if (tid < 128) {
        const float inv = gamma[o0 + tid] * rsqrtf(var[o0 + tid] + 1e-5f);
        sScale[tid] = inv;
        sBias[tid]  = beta[o0 + tid] - mean[o0 + tid] * inv;
    }

    const uint32_t sA = smem_u32(smem);
    const uint32_t sB = sA + 3 * A_STG;
    const int wm = wid & 3, wv = wid >> 2;

    float acc[2][8][4];
    #pragma unroll
    for (int i = 0; i < 2; ++i)
        #pragma unroll
        for (int j = 0; j < 8; ++j)
            #pragma unroll
            for (int q = 0; q < 4; ++q) acc[i][j][q] = 0.f;

    auto issue = [&](int s, int kc) {
        const uint32_t ab = sA + s * A_STG;
        const uint32_t bb = sB + s * B_STG;
        #pragma unroll
        for (int i = 0; i < 2; ++i) {       // A: 128 rows x 4 x 16B
            const int idx = tid + i * 256;
            const int row = idx >> 2, c = idx & 3;
            cp16(ab + row * 80 + c * 16, Wb + (size_t)row * D_ + kc + c * 8);
        }
        #pragma unroll
        for (int i = 0; i < 2; ++i) {       // B: 32 rows x 16 x 16B
            const int idx = tid + i * 256;
            const int row = idx >> 4, c = idx & 15;
            cp16(bb + row * 272 + c * 16, Xb + (size_t)(kc + row) * V_ + c * 8);
        }
        CP_COMMIT();
    };

    issue(0, 0);
    issue(1, 32);

    #pragma unroll 1
    for (int c = 0; c < 16; ++c) {
        if (c < 15) CP_WAIT1(); else CP_WAIT0();
        __syncthreads();
        if (c < 14) issue((c + 2) % 3, (c + 2) * 32);

        const int s = c % 3;
        const uint32_t aB = sA + s * A_STG;
        const uint32_t bB = sB + s * B_STG;

        #pragma unroll
        for (int kk = 0; kk < 2; ++kk) {
            uint32_t af[2][4];
            #pragma unroll
            for (int mt = 0; mt < 2; ++mt) {
                const int row = wm * 32 + mt * 16 + (lane & 15);
                ldsm_x4(af[mt], aB + row * 80 + kk * 32 + (lane >> 4) * 16);
            }
            uint32_t bfr[4][4];
            const int sub = lane >> 3;
            const int krow = kk * 16 + (sub & 1) * 8 + (lane & 7);
            #pragma unroll
            for (int g = 0; g < 4; ++g) {
                const int ncol = wv * 64 + g * 16 + (sub >> 1) * 8;
                ldsm_x4_t(bfr[g], bB + krow * 272 + ncol * 2);
            }
            #pragma unroll
            for (int mt = 0; mt < 2; ++mt)
                #pragma unroll
                for (int g = 0; g < 4; ++g) {
                    mma_bf16(acc[mt][g * 2 + 0], af[mt], bfr[g][0], bfr[g][1]);
                    mma_bf16(acc[mt][g * 2 + 1], af[mt], bfr[g][2], bfr[g][3]);
                }
        }
    }

    #pragma unroll
    for (int mt = 0; mt < 2; ++mt) {
        const int oL = wm * 32 + mt * 16 + (lane >> 2);
        #pragma unroll
        for (int h = 0; h < 2; ++h) {
            const int o = oL + h * 8;
            const float sc = sScale[o], bi = sBias[o];
            __nv_bfloat16* orow = O + ((size_t)z * D_ + o0 + o) * V_ + v0;
            #pragma unroll
            for (int nt = 0; nt < 8; ++nt) {
                const int v = wv * 64 + nt * 8 + (lane & 3) * 2;
                const float fa = acc[mt][nt][2 * h]     * sc + bi;
                const float fb = acc[mt][nt][2 * h + 1] * sc + bi;
                const __nv_bfloat162 h2 = __floats2bfloat162_rn(fa, fb);
                *(uint32_t*)(orow + v) = *(const uint32_t*)&h2;
            }
        }
    }
}

// ---------------------------------------------------------------------------
// Stage-3 GEMM (fp8 e4m3) + folded BN:
//   O[z][o][v] = BN_o( sum_d Wp8[o][d] * S8[z][v][d]^T )
// A [o][d] fp8 K-major; B (spikes) [v][d] fp8 K-major -> plain ldmatrix both.
// CTA 128x128, warps 4(o:32) x 2(v:64). K=512 in 8 chunks of 64.
// ---------------------------------------------------------------------------
#define F_STG 10240            // 128 rows * 80 B
#define SMEM_FP8 (6*F_STG)     // 61440

__global__ void __launch_bounds__(256, 2) gemm_bn_fp8(
    const uint8_t* __restrict__ W8,
    const uint8_t* __restrict__ S8,
    const float* __restrict__ gamma, const float* __restrict__ beta,
    const float* __restrict__ mean, const float* __restrict__ var,
    __nv_bfloat16* __restrict__ O)
{
    extern __shared__ __align__(16) char smem[];
    __shared__ float sScale[128], sBias[128];

    const int tid = threadIdx.x, wid = tid >> 5, lane = tid & 31;
    const int z = blockIdx.x, o0 = blockIdx.y * 128, v0 = blockIdx.z * 128;

    const uint8_t* Ab = W8 + (size_t)o0 * D_;
    const uint8_t* Bb = S8 + ((size_t)z * V_ + v0) * D_;

    if (tid < 128) {
        const float inv = gamma[o0 + tid] * rsqrtf(var[o0 + tid] + 1e-5f);
        sScale[tid] = inv;
        sBias[tid]  = beta[o0 + tid] - mean[o0 + tid] * inv;
    }

    const uint32_t sA = smem_u32(smem);
    const uint32_t sB = sA + 3 * F_STG;
    const int wm = wid & 3, wv = wid >> 2;

    float acc[2][8][4];
    #pragma unroll
    for (int i = 0; i < 2; ++i)
        #pragma unroll
        for (int j = 0; j < 8; ++j)
            #pragma unroll
            for (int q = 0; q < 4; ++q) acc[i][j][q] = 0.f;

    auto issue = [&](int s, int kc) {
        const uint32_t ab = sA + s * F_STG;
        const uint32_t bb = sB + s * F_STG;
        #pragma unroll
        for (int i = 0; i < 2; ++i) {       // A: 128 rows x 4 x 16B
            const int idx = tid + i * 256;
            const int row = idx >> 2, c = idx & 3;
            cp16(ab + row * 80 + c * 16, Ab + (size_t)row * D_ + kc + c * 16);
        }
        #pragma unroll
        for (int i = 0; i < 2; ++i) {       // B: 128 rows x 4 x 16B
            const int idx = tid + i * 256;
            const int row = idx >> 2, c = idx & 3;
            cp16(bb + row * 80 + c * 16, Bb + (size_t)row * D_ + kc + c * 16);
        }
        CP_COMMIT();
    };

    issue(0, 0);
    issue(1, 64);

    #pragma unroll 1
    for (int c = 0; c < 8; ++c) {
        if (c < 7) CP_WAIT1(); else CP_WAIT0();
        __syncthreads();
        if (c < 6) issue((c + 2) % 3, (c + 2) * 64);

        const int s = c % 3;
        const uint32_t aB = sA + s * F_STG;
        const uint32_t bB = sB + s * F_STG;

        #pragma unroll
        for (int kk = 0; kk < 2; ++kk) {
            uint32_t af[2][4];
            #pragma unroll
            for (int mt = 0; mt < 2; ++mt) {
                const int row = wm * 32 + mt * 16 + (lane & 15);
                ldsm_x4(af[mt], aB + row * 80 + kk * 32 + (lane >> 4) * 16);
            }
            uint32_t bfr[4][4];
            #pragma unroll
            for (int g = 0; g < 4; ++g) {
                const int row = wv * 64 + g * 16 + (lane & 15);
                ldsm_x4(bfr[g], bB + row * 80 + kk * 32 + (lane >> 4) * 16);
            }
            #pragma unroll
            for (int mt = 0; mt < 2; ++mt)
                #pragma unroll
                for (int g = 0; g < 4; ++g) {
                    mma_fp8(acc[mt][g * 2 + 0], af[mt], bfr[g][0], bfr[g][2]);
                    mma_fp8(acc[mt][g * 2 + 1], af[mt], bfr[g][1], bfr[g][3]);
                }
        }
    }

    #pragma unroll
    for (int mt = 0; mt < 2; ++mt) {
        const int oL = wm * 32 + mt * 16 + (lane >> 2);
        #pragma unroll
        for (int h = 0; h < 2; ++h) {
            const int o = oL + h * 8;
            const float sc = sScale[o], bi = sBias[o];
            __nv_bfloat16* orow = O + ((size_t)z * D_ + o0 + o) * V_ + v0;
            #pragma unroll
            for (int nt = 0; nt < 8; ++nt) {
                const int v = wv * 64 + nt * 8 + (lane & 3) * 2;
                const float fa = acc[mt][nt][2 * h]     * sc + bi;
                const float fb = acc[mt][nt][2 * h + 1] * sc + bi;
                const __nv_bfloat162 h2 = __floats2bfloat162_rn(fa, fb);
                *(uint32_t*)(orow + v) = *(const uint32_t*)&h2;
            }
        }
    }
}

// ---------------------------------------------------------------------------
// converters
// ---------------------------------------------------------------------------
__global__ void convert_x_kernel(const float* __restrict__ x, __nv_bfloat16* __restrict__ xb) {
    const size_t i = (size_t)blockIdx.x * blockDim.x + threadIdx.x;   // TOTAL/4
    const float4 f = ((const float4*)x)[i];
    const __nv_bfloat162 a = __floats2bfloat162_rn(f.x, f.y);
    const __nv_bfloat162 b = __floats2bfloat162_rn(f.z, f.w);
    uint2 u;
    u.x = *(const uint32_t*)&a;
    u.y = *(const uint32_t*)&b;
    ((uint2*)xb)[i] = u;
}
__global__ void convert_w_kernel(const float* __restrict__ s, __nv_bfloat16* __restrict__ d) {
    const int i = blockIdx.x * 256 + threadIdx.x;
    d[i] = __float2bfloat16(s[i]);
}
__global__ void convert_w8_kernel(const float* __restrict__ s, uint8_t* __restrict__ d) {
    const int i = blockIdx.x * 256 + threadIdx.x;
    d[i] = (uint8_t)__nv_cvt_float_to_fp8(s[i], __NV_SATFINITE, __NV_E4M3);
}

// ---------------------------------------------------------------------------
// LIF(q) -> q_sum -> gate LIF(0.5) -> LIF(k) -> spikes e4m3 to [z][v][d].
// Grid (b, h), 256 threads (v). SMEM byte-transpose for coalesced fp8 writes.
// ---------------------------------------------------------------------------
__global__ void lif_gate_kernel(const __nv_bfloat16* __restrict__ q,
                                const __nv_bfloat16* __restrict__ k,
                                uint8_t* __restrict__ sp8) {
    __shared__ uint8_t s8[4][256 * 36];   // [t][v][32 dd bytes, pitch 36]
    const int b = blockIdx.x, h = blockIdx.y;
    const int v = threadIdx.x, tid = threadIdx.x;

#define IDX(t, d) ((((size_t)((t) * B_ + b)) * D_ + h * 128 + (d)) * V_ + v)
    float qs0 = 0.f, qs1 = 0.f, qs2 = 0.f, qs3 = 0.f;
    #pragma unroll 4
    for (int d = 0; d < 128; ++d) {
        float vm = 0.f, s;
        vm = (vm + __bfloat162float(q[IDX(0, d)])) * 0.5f;
        s = (vm >= 1.f) ? 1.f : 0.f; qs0 += s; vm *= (1.f - s);
        vm = (vm + __bfloat162float(q[IDX(1, d)])) * 0.5f;
        s = (vm >= 1.f) ? 1.f : 0.f; qs1 += s; vm *= (1.f - s);
        vm = (vm + __bfloat162float(q[IDX(2, d)])) * 0.5f;
        s = (vm >= 1.f) ? 1.f : 0.f; qs2 += s; vm *= (1.f - s);
        vm = (vm + __bfloat162float(q[IDX(3, d)])) * 0.5f;
        s = (vm >= 1.f) ? 1.f : 0.f; qs3 += s;
    }
    uint8_t gateb[4];
    {
        float vg = 0.f;
        const float qs[4] = {qs0, qs1, qs2, qs3};
        #pragma unroll
        for (int t = 0; t < 4; ++t) {
            vg = (vg + qs[t]) * 0.5f;
            const float g = (vg >= 0.5f) ? 1.f : 0.f;
            gateb[t] = (g != 0.f) ? 0x38 : 0x00;
            vg *= (1.f - g);
        }
    }

    for (int cc = 0; cc < 4; ++cc) {
        #pragma unroll 4
        for (int j = 0; j < 32; ++j) {
            const int d = cc * 32 + j;
            float vm = 0.f;
            #pragma unroll
            for (int t = 0; t < 4; ++t) {
                vm = (vm + __bfloat162float(k[IDX(t, d)])) * 0.5f;
                const float s = (vm >= 1.f) ? 1.f : 0.f;
                s8[t][v * 36 + j] = (s != 0.f) ? gateb[t] : 0x00;
                vm *= (1.f - s);
            }
        }
        __syncthreads();
        #pragma unroll
        for (int t = 0; t < 4; ++t) {
            const uint32_t* sw = (const uint32_t*)&s8[t][0];
            uint32_t* outw = (uint32_t*)(sp8 + (size_t)(t * B_ + b) * V_ * D_);
            #pragma unroll
            for (int it = 0; it < 8; ++it) {
                const int idx = it * 256 + tid;          // 0..2047
                const int vv = idx >> 3, w = idx & 7;
                outw[(size_t)vv * 128 + h * 32 + cc * 8 + w] = sw[vv * 9 + w];
            }
        }
        __syncthreads();
    }
#undef IDX
}

// ---------------------------------------------------------------------------
// Final LIF(1.0) over t, [z][o][v] bf16 -> d_out [t][b][o][v] fp32 (4-wide)
// ---------------------------------------------------------------------------
__global__ void lif_final_kernel(const __nv_bfloat16* __restrict__ pre, float* __restrict__ out) {
    const size_t i4 = (size_t)blockIdx.x * blockDim.x + threadIdx.x;   // PLANE/4
    float v0 = 0.f, v1 = 0.f, v2 = 0.f, v3 = 0.f;
    #pragma unroll
    for (int t = 0; t < 4; ++t) {
        const uint2 u = ((const uint2*)(pre + (size_t)t * PLANE))[i4];
        const __nv_bfloat162 ha = *(const __nv_bfloat162*)&u.x;
        const __nv_bfloat162 hb = *(const __nv_bfloat162*)&u.y;
        v0 = (v0 + __bfloat162float(ha.x)) * 0.5f;
        v1 = (v1 + __bfloat162float(ha.y)) * 0.5f;
        v2 = (v2 + __bfloat162float(hb.x)) * 0.5f;
        v3 = (v3 + __bfloat162float(hb.y)) * 0.5f;
        const float s0 = (v0 >= 1.f) ? 1.f : 0.f;
        const float s1 = (v1 >= 1.f) ? 1.f : 0.f;
        const float s2 = (v2 >= 1.f) ? 1.f : 0.f;
        const float s3 = (v3 >= 1.f) ? 1.f : 0.f;
        ((float4*)(out + (size_t)t * PLANE))[i4] = make_float4(s0, s1, s2, s3);
        v0 *= (1.f - s0); v1 *= (1.f - s1); v2 *= (1.f - s2); v3 *= (1.f - s3);
    }
}

// ---------------------------------------------------------------------------
extern "C" void kernel_launch(void* const* d_in, const int* in_sizes, int n_in,
                              void* d_out, int out_size) {
    const float* x  = (const float*)d_in[0];
    const float* Wq = (const float*)d_in[1];
    const float* qg = (const float*)d_in[2];
    const float* qb = (const float*)d_in[3];
    const float* qm = (const float*)d_in[4];
    const float* qv = (const float*)d_in[5];
    const float* Wk = (const float*)d_in[6];
    const float* kg = (const float*)d_in[7];
    const float* kb = (const float*)d_in[8];
    const float* km = (const float*)d_in[9];
    const float* kv = (const float*)d_in[10];
    const float* Wp = (const float*)d_in[11];
    const float* pg = (const float*)d_in[12];
    const float* pb = (const float*)d_in[13];
    const float* pm = (const float*)d_in[14];
    const float* pv = (const float*)d_in[15];
    float* out = (float*)d_out;

    __nv_bfloat16 *xb, *qp, *kp, *wq, *wk;
    uint8_t *sp8, *wp8;
    cudaGetSymbolAddress((void**)&xb, g_xb);
    cudaGetSymbolAddress((void**)&qp, g_qpre);
    cudaGetSymbolAddress((void**)&kp, g_kpre);
    cudaGetSymbolAddress((void**)&sp8, g_sp8);
    cudaGetSymbolAddress((void**)&wq, g_wq);
    cudaGetSymbolAddress((void**)&wk, g_wk);
    cudaGetSymbolAddress((void**)&wp8, g_wp8);

    cudaFuncSetAttribute(gemm_bn_bf16, cudaFuncAttributeMaxDynamicSharedMemorySize, SMEM_BF16);
    cudaFuncSetAttribute(gemm_bn_fp8,  cudaFuncAttributeMaxDynamicSharedMemorySize, SMEM_FP8);

    convert_w_kernel<<<D_ * D_ / 256, 256>>>(Wq, wq);
    convert_w_kernel<<<D_ * D_ / 256, 256>>>(Wk, wk);
    convert_w8_kernel<<<D_ * D_ / 256, 256>>>(Wp, wp8);
    convert_x_kernel<<<TOTAL / 1024, 256>>>(x, xb);

    dim3 gg(Z_, D_ / 128, V_ / 128);   // (256, 4, 2)
    gemm_bn_bf16<<<gg, 256, SMEM_BF16>>>(wq, xb, qg, qb, qm, qv, qp);
    gemm_bn_bf16<<<gg, 256, SMEM_BF16>>>(wk, xb, kg, kb, km, kv, kp);
    lif_gate_kernel<<<dim3(B_, 4), 256>>>(qp, kp, sp8);
    gemm_bn_fp8<<<gg, 256, SMEM_FP8>>>(wp8, sp8, pg, pb, pm, pv, kp);
    lif_final_kernel<<<PLANE / 1024, 256>>>(kp, out);
}